// round 6
// baseline (speedup 1.0000x reference)
#include <cuda_runtime.h>
#include <cuda_bf16.h>
#include <cstdint>

#define BB 32
#define S_LEN 2048
#define EMB 256
#define NPOS (BB*S_LEN)
#define NSK 1000
#define NT128 16           // 128-col target tiles per sequence

// ---------- gathered operands (bf16, [pos][256]) ----------
__device__ __nv_bfloat16 g_srcA[NPOS*EMB];
__device__ __nv_bfloat16 g_srcB[NPOS*EMB];
__device__ __nv_bfloat16 g_tgtA[NPOS*EMB];
__device__ __nv_bfloat16 g_tgtB[NPOS*EMB];
__device__ float g_ts[NPOS];
__device__ float g_bias[NPOS];

// ---------- helpers ----------
__device__ __forceinline__ uint32_t smem_u32(const void* p){
    uint32_t a; asm("{ .reg .u64 t; cvta.to.shared.u64 t, %1; cvt.u32.u64 %0, t; }" : "=r"(a) : "l"(p));
    return a;
}
#define CP16(dst, src)  asm volatile("cp.async.cg.shared.global [%0], [%1], 16;" :: "r"(dst), "l"(src) : "memory")
#define CPCOMMIT()      asm volatile("cp.async.commit_group;" ::: "memory")
#define CPWAIT(n)       asm volatile("cp.async.wait_group %0;" :: "n"(n) : "memory")

#define LDSM4(f, addr) \
    asm volatile("ldmatrix.sync.aligned.m8n8.x4.shared.b16 {%0,%1,%2,%3}, [%4];" \
        : "=r"((f)[0]),"=r"((f)[1]),"=r"((f)[2]),"=r"((f)[3]) : "r"(addr))

#define MMA16816(d, a, b0, b1) \
    asm volatile("mma.sync.aligned.m16n8k16.row.col.f32.bf16.bf16.f32 " \
        "{%0,%1,%2,%3}, {%4,%5,%6,%7}, {%8,%9}, {%0,%1,%2,%3};" \
        : "+f"((d)[0]),"+f"((d)[1]),"+f"((d)[2]),"+f"((d)[3]) \
        : "r"((a)[0]),"r"((a)[1]),"r"((a)[2]),"r"((a)[3]), "r"(b0),"r"(b1))

__device__ __forceinline__ float flg2(float x){ float r; asm("lg2.approx.f32 %0, %1;" : "=f"(r) : "f"(x)); return r; }
__device__ __forceinline__ float fex2(float x){ float r; asm("ex2.approx.f32 %0, %1;" : "=f"(r) : "f"(x)); return r; }

// ---------- SMEM layout (dynamic, 1 CTA/SM) ----------
// tgtB: 4 K-planes x [128 x 128B] SW128     65536   @0
// tgtA: 65536                                        @65536
// ring: 3 stages x 32768 (2 K-planes each)  98304   @131072
// sTsT: float[128]                          512     @229376
// sPart: float[4][128]                      2048    @229888
#define OFF_TGTB   0
#define OFF_TGTA   65536
#define OFF_RING   131072
#define OFF_TST    229376
#define OFF_PART   229888
#define SMEM_BYTES 231936

// ---------- gather ----------
__global__ void gather_kernel(const int* __restrict__ skills, const int* __restrict__ problems,
                              const int* __restrict__ times,  const int* __restrict__ labels,
                              const float* __restrict__ aI, const float* __restrict__ aS,
                              const float* __restrict__ bI, const float* __restrict__ bS,
                              const float* __restrict__ pb, const float* __restrict__ sb)
{
    int idx = blockIdx.x * blockDim.x + threadIdx.x;
    if (idx >= NPOS * (EMB/4)) return;
    int pos = idx >> 6;
    int e   = (idx & 63) << 2;
    int sk  = skills[pos];
    int inter = sk + labels[pos] * NSK;
    float4 vA = *(const float4*)(aI + (size_t)inter*EMB + e);
    float4 vB = *(const float4*)(bI + (size_t)inter*EMB + e);
    float4 tA = *(const float4*)(aS + (size_t)sk*EMB + e);
    float4 tB = *(const float4*)(bS + (size_t)sk*EMB + e);
    size_t o = (size_t)pos*EMB + e;
    *(__nv_bfloat162*)(g_srcA + o)     = __floats2bfloat162_rn(vA.x, vA.y);
    *(__nv_bfloat162*)(g_srcA + o + 2) = __floats2bfloat162_rn(vA.z, vA.w);
    *(__nv_bfloat162*)(g_srcB + o)     = __floats2bfloat162_rn(vB.x, vB.y);
    *(__nv_bfloat162*)(g_srcB + o + 2) = __floats2bfloat162_rn(vB.z, vB.w);
    *(__nv_bfloat162*)(g_tgtA + o)     = __floats2bfloat162_rn(tA.x, tA.y);
    *(__nv_bfloat162*)(g_tgtA + o + 2) = __floats2bfloat162_rn(tA.z, tA.w);
    *(__nv_bfloat162*)(g_tgtB + o)     = __floats2bfloat162_rn(tB.x, tB.y);
    *(__nv_bfloat162*)(g_tgtB + o + 2) = __floats2bfloat162_rn(tB.z, tB.w);
    if ((idx & 63) == 0) {
        g_ts[pos]   = (float)times[pos] / 1000.0f;
        g_bias[pos] = pb[problems[pos]] + sb[sk];
    }
}

// issue one 32KB single-matrix chunk: g -> tile it=g>>2, q=g&3 (mat=q>>1, K-half h=q&1)
// Chunk = 2 K-planes of [128 rows x 64K(=128B)] SW128.
__device__ __forceinline__ void issue_chunk(uint32_t stage, int seq_base, int g, int tid)
{
    const int q = g & 3;
    const int h = q & 1;
    const int src_base = seq_base + (g >> 2) * 128;
    const __nv_bfloat16* gp = (q < 2) ? g_srcB : g_srcA;
    #pragma unroll
    for (int rep = 0; rep < 4; ++rep) {
        int j   = tid + rep*512;          // 0..2047 (16B units)
        int sp  = j >> 10;
        int rem = j & 1023;
        int r   = rem >> 3, u = rem & 7;
        uint32_t dst = stage + sp*16384 + r*128 + ((u ^ (r & 7)) << 4);
        CP16(dst, gp + (size_t)(src_base + r)*EMB + h*128 + sp*64 + u*8);
    }
}

// ---------- main HMMA kernel: 512 threads, 128x128 tile, 1 CTA/SM ----------
struct LaneCtx {
    uint32_t offA0, offA1, xA0, xA1, uAbit;
    uint32_t offB0, offB1, xB0, xB1, uBbit;
};

// one K=128 chunk of one GEMM: 2 K-planes x 4 kk, fragments double-buffered
__device__ __forceinline__ void compute_chunk(float (&acc)[2][4][4],
                                              uint32_t st, uint32_t tg, const LaneCtx& L)
{
    uint32_t fa0[2][4], fa1[2][4], fb0[2][4], fb1[2][4];
    #define LOADF(buf, t) do { \
        const int _sp = (t) >> 2, _kk = (t) & 3; \
        const uint32_t _sA = st + _sp*16384, _sB = tg + _sp*16384; \
        const uint32_t _uA = _kk*2 + L.uAbit, _uB = _kk*2 + L.uBbit; \
        LDSM4(fa0[buf], _sA + L.offA0 + (((_uA ^ L.xA0)) << 4)); \
        LDSM4(fa1[buf], _sA + L.offA1 + (((_uA ^ L.xA1)) << 4)); \
        LDSM4(fb0[buf], _sB + L.offB0 + (((_uB ^ L.xB0)) << 4)); \
        LDSM4(fb1[buf], _sB + L.offB1 + (((_uB ^ L.xB1)) << 4)); \
    } while(0)

    LOADF(0, 0);
    #pragma unroll
    for (int t = 0; t < 8; ++t) {
        const int cur = t & 1;
        if (t < 7) LOADF(cur ^ 1, t + 1);
        MMA16816(acc[0][0], fa0[cur], fb0[cur][0], fb0[cur][1]);
        MMA16816(acc[0][1], fa0[cur], fb0[cur][2], fb0[cur][3]);
        MMA16816(acc[0][2], fa0[cur], fb1[cur][0], fb1[cur][1]);
        MMA16816(acc[0][3], fa0[cur], fb1[cur][2], fb1[cur][3]);
        MMA16816(acc[1][0], fa1[cur], fb0[cur][0], fb0[cur][1]);
        MMA16816(acc[1][1], fa1[cur], fb0[cur][2], fb0[cur][3]);
        MMA16816(acc[1][2], fa1[cur], fb1[cur][0], fb1[cur][1]);
        MMA16816(acc[1][3], fa1[cur], fb1[cur][2], fb1[cur][3]);
    }
    #undef LOADF
}

__global__ void __launch_bounds__(512, 1) hawkes_mma(float* __restrict__ out)
{
    extern __shared__ char smem[];
    const uint32_t sb = smem_u32(smem);
    const int tid  = threadIdx.x;
    const int wid  = tid >> 5;
    const int lane = tid & 31;
    const int wm   = wid >> 2;       // source-row group (32 rows)
    const int wn   = wid & 3;        // target-col group (32 cols)

    const int bidx = blockIdx.x;
    const int jt = (NT128 - 1) - (bidx >> 5);   // big tiles first
    const int b  = bidx & 31;
    const int seq_base = b * S_LEN;
    const int col_base = seq_base + jt * 128;

    float* sTsT  = (float*)(smem + OFF_TST);
    float* sPart = (float*)(smem + OFF_PART);

    // ---- prologue: resident target tiles (group w/ chunk0) + chunk1 ----
    {
        #pragma unroll
        for (int rep = 0; rep < 16; ++rep) {
            int j   = tid + rep*512;           // 0..8191 (16B units)
            int mat = j >> 12;                 // 0: tgtB, 1: tgtA
            int rem = j & 4095;
            int kc4 = rem >> 10;               // K-plane
            int rr  = (rem >> 3) & 127;
            int u   = rem & 7;
            uint32_t dst = sb + (mat ? OFF_TGTA : OFF_TGTB) + kc4*16384 + rr*128 + ((u ^ (rr & 7)) << 4);
            const __nv_bfloat16* g = mat ? g_tgtA : g_tgtB;
            CP16(dst, g + (size_t)(col_base + rr)*EMB + kc4*64 + u*8);
        }
        issue_chunk(sb + OFF_RING, seq_base, 0, tid);
        CPCOMMIT();
        issue_chunk(sb + OFF_RING + 32768, seq_base, 1, tid);
        CPCOMMIT();
        if (tid < 128) sTsT[tid] = g_ts[col_base + tid];
    }

    // ---- per-lane constant addressing (round-3 proven formulas) ----
    LaneCtx L;
    {
        const int rA0 = wm*32 + (lane & 15);
        const int rA1 = rA0 + 16;
        L.offA0 = rA0*128; L.offA1 = rA1*128;
        L.xA0 = rA0 & 7;   L.xA1 = rA1 & 7;
        L.uAbit = (uint32_t)(lane >> 4);
        const int rB0 = wn*32 + (lane & 7) + ((lane >> 4) << 3);
        const int rB1 = rB0 + 16;
        L.offB0 = rB0*128; L.offB1 = rB1*128;
        L.xB0 = rB0 & 7;   L.xB1 = rB1 & 7;
        L.uBbit = (uint32_t)((lane >> 3) & 1);
    }

    float colsum[4][2];
    #pragma unroll
    for (int n = 0; n < 4; ++n) { colsum[n][0] = 0.f; colsum[n][1] = 0.f; }

    const int G = (jt + 1) * 4;
    const float NEG_INV_LN5 = -0.6213349345596119f;

    for (int it = 0; it <= jt; ++it) {
        const bool diag   = (it == jt);
        const bool active = !(diag && (wm > wn));   // fully-masked diag warps skip

        float accB[2][4][4];
        #pragma unroll
        for (int m = 0; m < 2; ++m)
            #pragma unroll
            for (int n = 0; n < 4; ++n)
                #pragma unroll
                for (int e = 0; e < 4; ++e) accB[m][n][e] = 0.f;

        // ===== beta phase: chunks it*4+0, it*4+1 =====
        #pragma unroll 1
        for (int q = 0; q < 2; ++q) {
            const int g = it*4 + q;
            CPWAIT(1);
            __syncthreads();
            if (g + 2 < G) issue_chunk(sb + OFF_RING + (uint32_t)((g + 2) % 3)*32768, seq_base, g + 2, tid);
            CPCOMMIT();
            if (active)
                compute_chunk(accB, sb + OFF_RING + (uint32_t)(g % 3)*32768,
                              sb + OFF_TGTB + (uint32_t)q*32768, L);
        }

        // source times for this tile
        const int src_base = seq_base + it * 128;
        float tsS[2][2];
        #pragma unroll
        for (int m = 0; m < 2; ++m) {
            tsS[m][0] = g_ts[src_base + wm*32 + m*16 + (lane >> 2)];
            tsS[m][1] = g_ts[src_base + wm*32 + m*16 + (lane >> 2) + 8];
        }

        float accA[2][4][4];
        #pragma unroll
        for (int m = 0; m < 2; ++m)
            #pragma unroll
            for (int n = 0; n < 4; ++n)
                #pragma unroll
                for (int e = 0; e < 4; ++e) accA[m][n][e] = 0.f;

        // ===== alpha phase: chunks it*4+2, +3; w-transform folded in =====
        #pragma unroll 1
        for (int q = 0; q < 2; ++q) {
            const int g = it*4 + 2 + q;
            CPWAIT(1);
            __syncthreads();
            if (g + 2 < G) issue_chunk(sb + OFF_RING + (uint32_t)((g + 2) % 3)*32768, seq_base, g + 2, tid);
            CPCOMMIT();
            if (active) {
                compute_chunk(accA, sb + OFF_RING + (uint32_t)(g % 3)*32768,
                              sb + OFF_TGTA + (uint32_t)q*32768, L);
                // transform 2 n-groups of beta accumulators into weights
                // (MUFU overlaps the in-flight HMMAs above)
                #pragma unroll
                for (int hh = 0; hh < 2; ++hh) {
                    const int ng = q*2 + hh;
                    const int c0 = wn*32 + ng*8 + 2*(lane & 3);
                    #pragma unroll
                    for (int m = 0; m < 2; ++m)
                        #pragma unroll
                        for (int e = 0; e < 4; ++e) {
                            float beta = fminf(fmaxf(accB[m][ng][e] + 1.0f, 0.0f), 10.0f);
                            float d    = fabsf(tsS[m][e >> 1] - sTsT[c0 + (e & 1)]) + 1e-10f;
                            accB[m][ng][e] = fex2(beta * (flg2(d) * NEG_INV_LN5));
                        }
                }
            }
        }

        // ===== short FMA tail =====
        if (active) {
            #pragma unroll
            for (int m = 0; m < 2; ++m) {
                const int rlo = wm*32 + m*16 + (lane >> 2);
                #pragma unroll
                for (int n = 0; n < 4; ++n) {
                    const int c0 = wn*32 + n*8 + 2*(lane & 3);
                    #pragma unroll
                    for (int e = 0; e < 4; ++e) {
                        const int r_l = rlo + ((e < 2) ? 0 : 8);
                        const int c_l = c0 + (e & 1);
                        if (!diag || (r_l < c_l))
                            colsum[n][e & 1] += accA[m][n][e] * accB[m][n][e];
                    }
                }
            }
        }
    }

    // ---- cross-lane column reduce (lanes sharing a column differ in bits 2..4) ----
    #pragma unroll
    for (int n = 0; n < 4; ++n)
        #pragma unroll
        for (int p = 0; p < 2; ++p) {
            float v = colsum[n][p];
            v += __shfl_xor_sync(0xffffffffu, v, 4);
            v += __shfl_xor_sync(0xffffffffu, v, 8);
            v += __shfl_xor_sync(0xffffffffu, v, 16);
            colsum[n][p] = v;
        }
    __syncthreads();
    if (lane < 4) {
        #pragma unroll
        for (int n = 0; n < 4; ++n) {
            int c = wn*32 + n*8 + 2*lane;
            sPart[wm*128 + c]     = colsum[n][0];
            sPart[wm*128 + c + 1] = colsum[n][1];
        }
    }
    __syncthreads();

    if (tid < 128) {
        float s = sPart[tid] + sPart[128 + tid] + sPart[256 + tid] + sPart[384 + tid];
        float h = g_bias[col_base + tid] + s;
        out[col_base + tid] = 1.0f / (1.0f + fex2(-h * 1.4426950408889634f));
    }
}

extern "C" void kernel_launch(void* const* d_in, const int* in_sizes, int n_in,
                              void* d_out, int out_size)
{
    const int*   skills   = (const int*)d_in[0];
    const int*   problems = (const int*)d_in[1];
    const int*   times    = (const int*)d_in[2];
    const int*   labels   = (const int*)d_in[3];
    const float* aI = (const float*)d_in[4];
    const float* aS = (const float*)d_in[5];
    const float* bI = (const float*)d_in[6];
    const float* bS = (const float*)d_in[7];
    const float* pb = (const float*)d_in[8];
    const float* sb = (const float*)d_in[9];
    float* out = (float*)d_out;

    static bool attr_done = false;
    if (!attr_done) {
        cudaFuncSetAttribute(hawkes_mma, cudaFuncAttributeMaxDynamicSharedMemorySize, SMEM_BYTES);
        attr_done = true;
    }

    int total = NPOS * (EMB/4);
    gather_kernel<<<(total + 255) / 256, 256>>>(skills, problems, times, labels,
                                                aI, aS, bI, bS, pb, sb);
    hawkes_mma<<<NT128 * BB, 512, SMEM_BYTES>>>(out);
}

// round 11
// speedup vs baseline: 1.2050x; 1.2050x over previous
#include <cuda_runtime.h>
#include <cuda_bf16.h>
#include <cstdint>

#define BB 32
#define S_LEN 2048
#define EMB 256
#define NPOS (BB*S_LEN)
#define NSK 1000
#define NT128 16

// ---------- gathered operands (bf16, [pos][256]) ----------
__device__ __nv_bfloat16 g_srcA[NPOS*EMB];
__device__ __nv_bfloat16 g_srcB[NPOS*EMB];
__device__ __nv_bfloat16 g_tgtA[NPOS*EMB];
__device__ __nv_bfloat16 g_tgtB[NPOS*EMB];
__device__ float g_ts[NPOS];
__device__ float g_bias[NPOS];

// ---------- helpers ----------
__device__ __forceinline__ uint32_t smem_u32(const void* p){
    uint32_t a; asm("{ .reg .u64 t; cvta.to.shared.u64 t, %1; cvt.u32.u64 %0, t; }" : "=r"(a) : "l"(p));
    return a;
}
#define CP16(dst, src)  asm volatile("cp.async.cg.shared.global [%0], [%1], 16;" :: "r"(dst), "l"(src) : "memory")
#define CPCOMMIT()      asm volatile("cp.async.commit_group;" ::: "memory")
#define CPWAIT(n)       asm volatile("cp.async.wait_group %0;" :: "n"(n) : "memory")

#define LDSM4(r0,r1,r2,r3,addr) \
    asm volatile("ldmatrix.sync.aligned.m8n8.x4.shared.b16 {%0,%1,%2,%3}, [%4];" \
        : "=r"(r0),"=r"(r1),"=r"(r2),"=r"(r3) : "r"(addr))

#define MMA16816(d, a, b0, b1) \
    asm volatile("mma.sync.aligned.m16n8k16.row.col.f32.bf16.bf16.f32 " \
        "{%0,%1,%2,%3}, {%4,%5,%6,%7}, {%8,%9}, {%0,%1,%2,%3};" \
        : "+f"((d)[0]),"+f"((d)[1]),"+f"((d)[2]),"+f"((d)[3]) \
        : "r"((a)[0]),"r"((a)[1]),"r"((a)[2]),"r"((a)[3]), "r"(b0),"r"(b1))

__device__ __forceinline__ float flg2(float x){ float r; asm("lg2.approx.f32 %0, %1;" : "=f"(r) : "f"(x)); return r; }
__device__ __forceinline__ float fex2(float x){ float r; asm("ex2.approx.f32 %0, %1;" : "=f"(r) : "f"(x)); return r; }

// ---------- SMEM layout (dynamic, 1 CTA/SM) ----------
// tgtA: 4 K-planes x [128 x 128B] SW128     65536   @0
// tgtB: 65536                                       @65536
// ring: 3 stages x 32768 (srcA 16K + srcB 16K)      @131072
// sTsT: float[128]                                  @229376
// sPart: float[4][128]                              @229888
#define OFF_TGTA   0
#define OFF_TGTB   65536
#define OFF_RING   131072
#define OFF_TST    229376
#define OFF_PART   229888
#define SMEM_BYTES 231936

// ---------- gather ----------
__global__ void gather_kernel(const int* __restrict__ skills, const int* __restrict__ problems,
                              const int* __restrict__ times,  const int* __restrict__ labels,
                              const float* __restrict__ aI, const float* __restrict__ aS,
                              const float* __restrict__ bI, const float* __restrict__ bS,
                              const float* __restrict__ pb, const float* __restrict__ sb)
{
    int idx = blockIdx.x * blockDim.x + threadIdx.x;
    if (idx >= NPOS * (EMB/4)) return;
    int pos = idx >> 6;
    int e   = (idx & 63) << 2;
    int sk  = skills[pos];
    int inter = sk + labels[pos] * NSK;
    float4 vA = *(const float4*)(aI + (size_t)inter*EMB + e);
    float4 vB = *(const float4*)(bI + (size_t)inter*EMB + e);
    float4 tA = *(const float4*)(aS + (size_t)sk*EMB + e);
    float4 tB = *(const float4*)(bS + (size_t)sk*EMB + e);
    size_t o = (size_t)pos*EMB + e;
    *(__nv_bfloat162*)(g_srcA + o)     = __floats2bfloat162_rn(vA.x, vA.y);
    *(__nv_bfloat162*)(g_srcA + o + 2) = __floats2bfloat162_rn(vA.z, vA.w);
    *(__nv_bfloat162*)(g_srcB + o)     = __floats2bfloat162_rn(vB.x, vB.y);
    *(__nv_bfloat162*)(g_srcB + o + 2) = __floats2bfloat162_rn(vB.z, vB.w);
    *(__nv_bfloat162*)(g_tgtA + o)     = __floats2bfloat162_rn(tA.x, tA.y);
    *(__nv_bfloat162*)(g_tgtA + o + 2) = __floats2bfloat162_rn(tA.z, tA.w);
    *(__nv_bfloat162*)(g_tgtB + o)     = __floats2bfloat162_rn(tB.x, tB.y);
    *(__nv_bfloat162*)(g_tgtB + o + 2) = __floats2bfloat162_rn(tB.z, tB.w);
    if ((idx & 63) == 0) {
        g_ts[pos]   = (float)times[pos] / 1000.0f;
        g_bias[pos] = pb[problems[pos]] + sb[sk];
    }
}

// issue one 32KB chunk: K=64 slice (kc = g&3) of BOTH src matrices for tile it = g>>2.
// srcA @ stage+0, srcB @ stage+16384; [128 rows x 128B], SW128 swizzled.
__device__ __forceinline__ void issue_chunk(uint32_t stage, int seq_base, int g, int tid)
{
    const int kc = g & 3;
    const int src_base = seq_base + (g >> 2) * 128;
    #pragma unroll
    for (int rep = 0; rep < 4; ++rep) {
        int j   = tid + rep*512;          // 0..2047 (16B units)
        int mat = j >> 10;                // 0: A, 1: B
        int rem = j & 1023;
        int r   = rem >> 3, u = rem & 7;
        uint32_t dst = stage + mat*16384 + r*128 + ((u ^ (r & 7)) << 4);
        const __nv_bfloat16* gp = mat ? g_srcB : g_srcA;
        CP16(dst, gp + (size_t)(src_base + r)*EMB + kc*64 + u*8);
    }
}

// ---------- main HMMA kernel: 512 threads, 128x128 tile, 1 CTA/SM ----------
__global__ void __launch_bounds__(512, 1) hawkes_mma(float* __restrict__ out)
{
    extern __shared__ char smem[];
    const uint32_t sb = smem_u32(smem);
    const int tid  = threadIdx.x;
    const int wid  = tid >> 5;
    const int lane = tid & 31;
    const int wm   = wid >> 2;       // source-row group (32 rows)
    const int wn   = wid & 3;        // target-col group (32 cols)

    const int bidx = blockIdx.x;
    const int jt = (NT128 - 1) - (bidx >> 5);   // big tiles first
    const int b  = bidx & 31;
    const int seq_base = b * S_LEN;
    const int col_base = seq_base + jt * 128;

    float* sTsT  = (float*)(smem + OFF_TST);
    float* sPart = (float*)(smem + OFF_PART);

    // ---- prologue: resident target tiles (+chunk0 = group0), chunk1 = group1 ----
    {
        #pragma unroll
        for (int rep = 0; rep < 16; ++rep) {
            int j   = tid + rep*512;           // 0..8191 (16B units)
            int mat = j >> 12;                 // 0: tgtA, 1: tgtB
            int rem = j & 4095;
            int kc4 = rem >> 10;               // K-plane
            int rr  = (rem >> 3) & 127;
            int u   = rem & 7;
            uint32_t dst = sb + (mat ? OFF_TGTB : OFF_TGTA) + kc4*16384 + rr*128 + ((u ^ (rr & 7)) << 4);
            const __nv_bfloat16* g = mat ? g_tgtB : g_tgtA;
            CP16(dst, g + (size_t)(col_base + rr)*EMB + kc4*64 + u*8);
        }
        issue_chunk(sb + OFF_RING, seq_base, 0, tid);
        CPCOMMIT();                                   // group 0: tgt + chunk0
        issue_chunk(sb + OFF_RING + 32768, seq_base, 1, tid);
        CPCOMMIT();                                   // group 1: chunk1
        if (tid < 128) sTsT[tid] = g_ts[col_base + tid];
    }

    // ---- per-lane constant addressing (R3 formulas) ----
    const int rA0 = wm*32 + (lane & 15);
    const int rA1 = rA0 + 16;
    const uint32_t offA0 = rA0*128, offA1 = rA1*128;
    const uint32_t xA0 = rA0 & 7,  xA1 = rA1 & 7;
    const uint32_t uAbit = (uint32_t)(lane >> 4);

    const int rB0 = wn*32 + (lane & 7) + ((lane >> 4) << 3);
    const int rB1 = rB0 + 16;
    const uint32_t offB0 = rB0*128, offB1 = rB1*128;
    const uint32_t xB0 = rB0 & 7,  xB1 = rB1 & 7;
    const uint32_t uBbit = (uint32_t)((lane >> 3) & 1);

    float tsT[4][2];
    #pragma unroll
    for (int n = 0; n < 4; ++n) {
        int c0 = wn*32 + n*8 + 2*(lane & 3);
        tsT[n][0] = g_ts[col_base + c0];
        tsT[n][1] = g_ts[col_base + c0 + 1];
    }

    float colsum[4][2];
    #pragma unroll
    for (int n = 0; n < 4; ++n) { colsum[n][0] = 0.f; colsum[n][1] = 0.f; }

    const int G = (jt + 1) * 4;
    const float NEG_INV_LN5 = -0.6213349345596119f;

    for (int it = 0; it <= jt; ++it) {
        const bool diag   = (it == jt);
        const bool active = !(diag && (wm > wn));   // fully-masked diag warps idle

        float accA[2][4][4], accB[2][4][4];
        #pragma unroll
        for (int m = 0; m < 2; ++m)
            #pragma unroll
            for (int n = 0; n < 4; ++n)
                #pragma unroll
                for (int e = 0; e < 4; ++e) { accA[m][n][e] = 0.f; accB[m][n][e] = 0.f; }

        #pragma unroll 1
        for (int kc = 0; kc < 4; ++kc) {
            const int g = it*4 + kc;
            CPWAIT(1);                // chunk g arrived (g+1 may be in flight)
            __syncthreads();          // visibility + stage (g+2)%3 free (consumed at g-1)
            if (g + 2 < G)
                issue_chunk(sb + OFF_RING + (uint32_t)((g + 2) % 3)*32768, seq_base, g + 2, tid);
            CPCOMMIT();

            if (active) {
                const uint32_t stA = sb + OFF_RING + (uint32_t)(g % 3)*32768;
                const uint32_t stB = stA + 16384;
                const uint32_t tgA = sb + OFF_TGTA + (uint32_t)kc*16384;
                const uint32_t tgB = sb + OFF_TGTB + (uint32_t)kc*16384;

                #pragma unroll
                for (int kk = 0; kk < 4; ++kk) {
                    const uint32_t uA = kk*2 + uAbit;
                    const uint32_t uB = kk*2 + uBbit;
                    uint32_t aA0[4], aA1[4], aB0[4], aB1[4];
                    uint32_t bA0[4], bA1[4], bB0[4], bB1[4];
                    LDSM4(aA0[0],aA0[1],aA0[2],aA0[3], stA + offA0 + (((uA ^ xA0)) << 4));
                    LDSM4(aA1[0],aA1[1],aA1[2],aA1[3], stA + offA1 + (((uA ^ xA1)) << 4));
                    LDSM4(aB0[0],aB0[1],aB0[2],aB0[3], stB + offA0 + (((uA ^ xA0)) << 4));
                    LDSM4(aB1[0],aB1[1],aB1[2],aB1[3], stB + offA1 + (((uA ^ xA1)) << 4));
                    LDSM4(bA0[0],bA0[1],bA0[2],bA0[3], tgA + offB0 + (((uB ^ xB0)) << 4));
                    LDSM4(bA1[0],bA1[1],bA1[2],bA1[3], tgA + offB1 + (((uB ^ xB1)) << 4));
                    LDSM4(bB0[0],bB0[1],bB0[2],bB0[3], tgB + offB0 + (((uB ^ xB0)) << 4));
                    LDSM4(bB1[0],bB1[1],bB1[2],bB1[3], tgB + offB1 + (((uB ^ xB1)) << 4));

                    MMA16816(accA[0][0], aA0, bA0[0], bA0[1]);
                    MMA16816(accA[0][1], aA0, bA0[2], bA0[3]);
                    MMA16816(accA[0][2], aA0, bA1[0], bA1[1]);
                    MMA16816(accA[0][3], aA0, bA1[2], bA1[3]);
                    MMA16816(accA[1][0], aA1, bA0[0], bA0[1]);
                    MMA16816(accA[1][1], aA1, bA0[2], bA0[3]);
                    MMA16816(accA[1][2], aA1, bA1[0], bA1[1]);
                    MMA16816(accA[1][3], aA1, bA1[2], bA1[3]);

                    MMA16816(accB[0][0], aB0, bB0[0], bB0[1]);
                    MMA16816(accB[0][1], aB0, bB0[2], bB0[3]);
                    MMA16816(accB[0][2], aB0, bB1[0], bB1[1]);
                    MMA16816(accB[0][3], aB0, bB1[2], bB1[3]);
                    MMA16816(accB[1][0], aB1, bB0[0], bB0[1]);
                    MMA16816(accB[1][1], aB1, bB0[2], bB0[3]);
                    MMA16816(accB[1][2], aB1, bB1[0], bB1[1]);
                    MMA16816(accB[1][3], aB1, bB1[2], bB1[3]);
                }
            }
        }

        // ---- epilogue for this source tile ----
        if (active) {
            const int src_base = seq_base + it * 128;
            const bool edge = diag && (wm == wn);   // only case needing the predicate
            #pragma unroll
            for (int m = 0; m < 2; ++m) {
                const int rlo = wm*32 + m*16 + (lane >> 2);
                const float tsS_lo = g_ts[src_base + rlo];
                const float tsS_hi = g_ts[src_base + rlo + 8];
                #pragma unroll
                for (int n = 0; n < 4; ++n) {
                    #pragma unroll
                    for (int e = 0; e < 4; ++e) {
                        const float tsS = (e < 2) ? tsS_lo : tsS_hi;
                        float beta = fminf(fmaxf(accB[m][n][e] + 1.0f, 0.0f), 10.0f);
                        float d    = fabsf(tsS - tsT[n][e & 1]) + 1e-10f;
                        float w    = fex2(beta * (flg2(d) * NEG_INV_LN5));
                        float cr   = accA[m][n][e] * w;
                        if (edge) {
                            const int r_l = (wm*32 + m*16 + (lane >> 2)) + ((e < 2) ? 0 : 8);
                            const int c_l = wn*32 + n*8 + 2*(lane & 3) + (e & 1);
                            if (r_l < c_l) colsum[n][e & 1] += cr;
                        } else {
                            colsum[n][e & 1] += cr;
                        }
                    }
                }
            }
        }
    }

    // ---- cross-lane column reduce (lanes sharing a column differ in bits 2..4) ----
    #pragma unroll
    for (int n = 0; n < 4; ++n)
        #pragma unroll
        for (int p = 0; p < 2; ++p) {
            float v = colsum[n][p];
            v += __shfl_xor_sync(0xffffffffu, v, 4);
            v += __shfl_xor_sync(0xffffffffu, v, 8);
            v += __shfl_xor_sync(0xffffffffu, v, 16);
            colsum[n][p] = v;
        }
    __syncthreads();
    if (lane < 4) {
        #pragma unroll
        for (int n = 0; n < 4; ++n) {
            int c = wn*32 + n*8 + 2*lane;
            sPart[wm*128 + c]     = colsum[n][0];
            sPart[wm*128 + c + 1] = colsum[n][1];
        }
    }
    __syncthreads();

    if (tid < 128) {
        float s = sPart[tid] + sPart[128 + tid] + sPart[256 + tid] + sPart[384 + tid];
        float h = g_bias[col_base + tid] + s;
        out[col_base + tid] = 1.0f / (1.0f + fex2(-h * 1.4426950408889634f));
    }
}

extern "C" void kernel_launch(void* const* d_in, const int* in_sizes, int n_in,
                              void* d_out, int out_size)
{
    const int*   skills   = (const int*)d_in[0];
    const int*   problems = (const int*)d_in[1];
    const int*   times    = (const int*)d_in[2];
    const int*   labels   = (const int*)d_in[3];
    const float* aI = (const float*)d_in[4];
    const float* aS = (const float*)d_in[5];
    const float* bI = (const float*)d_in[6];
    const float* bS = (const float*)d_in[7];
    const float* pb = (const float*)d_in[8];
    const float* sb = (const float*)d_in[9];
    float* out = (float*)d_out;

    static bool attr_done = false;
    if (!attr_done) {
        cudaFuncSetAttribute(hawkes_mma, cudaFuncAttributeMaxDynamicSharedMemorySize, SMEM_BYTES);
        attr_done = true;
    }

    int total = NPOS * (EMB/4);
    gather_kernel<<<(total + 255) / 256, 256>>>(skills, problems, times, labels,
                                                aI, aS, bI, bS, pb, sb);
    hawkes_mma<<<NT128 * BB, 512, SMEM_BYTES>>>(out);
}

// round 13
// speedup vs baseline: 1.2146x; 1.0080x over previous
#include <cuda_runtime.h>
#include <cuda_bf16.h>
#include <cstdint>

#define BB 32
#define S_LEN 2048
#define EMB 256
#define NPOS (BB*S_LEN)
#define NSK 1000
#define NT128 16

// ---------- gathered operands (bf16, [pos][256]) ----------
__device__ __nv_bfloat16 g_srcA[NPOS*EMB];
__device__ __nv_bfloat16 g_srcB[NPOS*EMB];
__device__ __nv_bfloat16 g_tgtA[NPOS*EMB];
__device__ __nv_bfloat16 g_tgtB[NPOS*EMB];
__device__ float g_ts[NPOS];
__device__ float g_bias[NPOS];

// ---------- helpers ----------
__device__ __forceinline__ uint32_t smem_u32(const void* p){
    uint32_t a; asm("{ .reg .u64 t; cvta.to.shared.u64 t, %1; cvt.u32.u64 %0, t; }" : "=r"(a) : "l"(p));
    return a;
}
#define CP16(dst, src)  asm volatile("cp.async.cg.shared.global [%0], [%1], 16;" :: "r"(dst), "l"(src) : "memory")
#define CPCOMMIT()      asm volatile("cp.async.commit_group;" ::: "memory")
#define CPWAIT(n)       asm volatile("cp.async.wait_group %0;" :: "n"(n) : "memory")

#define LDSM4(r0,r1,r2,r3,addr) \
    asm volatile("ldmatrix.sync.aligned.m8n8.x4.shared.b16 {%0,%1,%2,%3}, [%4];" \
        : "=r"(r0),"=r"(r1),"=r"(r2),"=r"(r3) : "r"(addr))

#define MMA16816(d, a, b0, b1) \
    asm volatile("mma.sync.aligned.m16n8k16.row.col.f32.bf16.bf16.f32 " \
        "{%0,%1,%2,%3}, {%4,%5,%6,%7}, {%8,%9}, {%0,%1,%2,%3};" \
        : "+f"((d)[0]),"+f"((d)[1]),"+f"((d)[2]),"+f"((d)[3]) \
        : "r"((a)[0]),"r"((a)[1]),"r"((a)[2]),"r"((a)[3]), "r"(b0),"r"(b1))

__device__ __forceinline__ float flg2(float x){ float r; asm("lg2.approx.f32 %0, %1;" : "=f"(r) : "f"(x)); return r; }
__device__ __forceinline__ float fex2(float x){ float r; asm("ex2.approx.f32 %0, %1;" : "=f"(r) : "f"(x)); return r; }

// ---------- SMEM layout (dynamic, 1 CTA/SM) ----------
#define OFF_TGTA   0
#define OFF_TGTB   65536
#define OFF_RING   131072
#define OFF_TST    229376
#define OFF_PART   229888
#define SMEM_BYTES 231936

// ---------- gather ----------
__global__ void gather_kernel(const int* __restrict__ skills, const int* __restrict__ problems,
                              const int* __restrict__ times,  const int* __restrict__ labels,
                              const float* __restrict__ aI, const float* __restrict__ aS,
                              const float* __restrict__ bI, const float* __restrict__ bS,
                              const float* __restrict__ pb, const float* __restrict__ sb)
{
    int idx = blockIdx.x * blockDim.x + threadIdx.x;
    if (idx >= NPOS * (EMB/4)) return;
    int pos = idx >> 6;
    int e   = (idx & 63) << 2;
    int sk  = skills[pos];
    int inter = sk + labels[pos] * NSK;
    float4 vA = *(const float4*)(aI + (size_t)inter*EMB + e);
    float4 vB = *(const float4*)(bI + (size_t)inter*EMB + e);
    float4 tA = *(const float4*)(aS + (size_t)sk*EMB + e);
    float4 tB = *(const float4*)(bS + (size_t)sk*EMB + e);
    size_t o = (size_t)pos*EMB + e;

    union { __nv_bfloat162 h[2]; uint64_t ll; } pk;
    pk.h[0] = __floats2bfloat162_rn(vA.x, vA.y);
    pk.h[1] = __floats2bfloat162_rn(vA.z, vA.w);
    *(uint64_t*)(g_srcA + o) = pk.ll;
    pk.h[0] = __floats2bfloat162_rn(vB.x, vB.y);
    pk.h[1] = __floats2bfloat162_rn(vB.z, vB.w);
    *(uint64_t*)(g_srcB + o) = pk.ll;
    pk.h[0] = __floats2bfloat162_rn(tA.x, tA.y);
    pk.h[1] = __floats2bfloat162_rn(tA.z, tA.w);
    *(uint64_t*)(g_tgtA + o) = pk.ll;
    pk.h[0] = __floats2bfloat162_rn(tB.x, tB.y);
    pk.h[1] = __floats2bfloat162_rn(tB.z, tB.w);
    *(uint64_t*)(g_tgtB + o) = pk.ll;

    if ((idx & 63) == 0) {
        g_ts[pos]   = (float)times[pos] / 1000.0f;
        g_bias[pos] = pb[problems[pos]] + sb[sk];
    }
}

// issue one 32KB chunk: K=64 slice (kc = g&3) of BOTH src matrices for tile it = g>>2.
__device__ __forceinline__ void issue_chunk(uint32_t stage, int seq_base, int g, int tid)
{
    const int kc = g & 3;
    const int src_base = seq_base + (g >> 2) * 128;
    #pragma unroll
    for (int rep = 0; rep < 4; ++rep) {
        int j   = tid + rep*512;          // 0..2047 (16B units)
        int mat = j >> 10;                // 0: A, 1: B
        int rem = j & 1023;
        int r   = rem >> 3, u = rem & 7;
        uint32_t dst = stage + mat*16384 + r*128 + ((u ^ (r & 7)) << 4);
        const __nv_bfloat16* gp = mat ? g_srcB : g_srcA;
        CP16(dst, gp + (size_t)(src_base + r)*EMB + kc*64 + u*8);
    }
}

// ---------- main HMMA kernel: 512 threads, 128x128 tile, 1 CTA/SM ----------
__global__ void __launch_bounds__(512, 1) hawkes_mma(float* __restrict__ out)
{
    extern __shared__ char smem[];
    const uint32_t sb = smem_u32(smem);
    const int tid  = threadIdx.x;
    const int wid  = tid >> 5;
    const int lane = tid & 31;
    const int wm   = wid >> 2;       // source-row group (32 rows)
    const int wn   = wid & 3;        // target-col group (32 cols)

    const int bidx = blockIdx.x;
    const int jt = (NT128 - 1) - (bidx >> 5);   // big tiles first
    const int b  = bidx & 31;
    const int seq_base = b * S_LEN;
    const int col_base = seq_base + jt * 128;

    float* sTsT  = (float*)(smem + OFF_TST);
    float* sPart = (float*)(smem + OFF_PART);

    // ---- prologue: resident target tiles (+chunk0 = group0), chunk1 = group1 ----
    {
        #pragma unroll
        for (int rep = 0; rep < 16; ++rep) {
            int j   = tid + rep*512;           // 0..8191 (16B units)
            int mat = j >> 12;                 // 0: tgtA, 1: tgtB
            int rem = j & 4095;
            int kc4 = rem >> 10;               // K-plane
            int rr  = (rem >> 3) & 127;
            int u   = rem & 7;
            uint32_t dst = sb + (mat ? OFF_TGTB : OFF_TGTA) + kc4*16384 + rr*128 + ((u ^ (rr & 7)) << 4);
            const __nv_bfloat16* g = mat ? g_tgtB : g_tgtA;
            CP16(dst, g + (size_t)(col_base + rr)*EMB + kc4*64 + u*8);
        }
        issue_chunk(sb + OFF_RING, seq_base, 0, tid);
        CPCOMMIT();                                   // group 0: tgt + chunk0
        issue_chunk(sb + OFF_RING + 32768, seq_base, 1, tid);
        CPCOMMIT();                                   // group 1: chunk1
        if (tid < 128) sTsT[tid] = g_ts[col_base + tid];
    }

    // ---- per-lane constant addressing ----
    const int rA0 = wm*32 + (lane & 15);
    const int rA1 = rA0 + 16;
    const uint32_t offA0 = rA0*128, offA1 = rA1*128;
    const uint32_t xA0 = rA0 & 7,  xA1 = rA1 & 7;
    const uint32_t uAbit = (uint32_t)(lane >> 4);

    const int rB0 = wn*32 + (lane & 7) + ((lane >> 4) << 3);
    const int rB1 = rB0 + 16;
    const uint32_t offB0 = rB0*128, offB1 = rB1*128;
    const uint32_t xB0 = rB0 & 7,  xB1 = rB1 & 7;
    const uint32_t uBbit = (uint32_t)((lane >> 3) & 1);

    float colsum[4][2];
    #pragma unroll
    for (int n = 0; n < 4; ++n) { colsum[n][0] = 0.f; colsum[n][1] = 0.f; }

    const int G = (jt + 1) * 4;
    const float NEG_INV_LN5 = -0.6213349345596119f;

    for (int it = 0; it <= jt; ++it) {
        const bool diag   = (it == jt);
        const bool active = !(diag && (wm > wn));   // fully-masked diag warps idle

        // tsS hoisted to tile start: LDG latency hidden under the 4-chunk k-loop
        const int src_base = seq_base + it * 128;
        float tsS[2][2];
        #pragma unroll
        for (int m = 0; m < 2; ++m) {
            tsS[m][0] = g_ts[src_base + wm*32 + m*16 + (lane >> 2)];
            tsS[m][1] = g_ts[src_base + wm*32 + m*16 + (lane >> 2) + 8];
        }

        float accA[2][4][4], accB[2][4][4];
        #pragma unroll
        for (int m = 0; m < 2; ++m)
            #pragma unroll
            for (int n = 0; n < 4; ++n)
                #pragma unroll
                for (int e = 0; e < 4; ++e) { accA[m][n][e] = 0.f; accB[m][n][e] = 0.f; }

        #pragma unroll 1
        for (int kc = 0; kc < 4; ++kc) {
            const int g = it*4 + kc;
            CPWAIT(1);                // chunk g arrived (g+1 may be in flight)
            __syncthreads();          // visibility + stage (g+2)%3 free
            if (g + 2 < G)
                issue_chunk(sb + OFF_RING + (uint32_t)((g + 2) % 3)*32768, seq_base, g + 2, tid);
            CPCOMMIT();

            if (active) {
                const uint32_t stA = sb + OFF_RING + (uint32_t)(g % 3)*32768;
                const uint32_t stB = stA + 16384;
                const uint32_t tgA = sb + OFF_TGTA + (uint32_t)kc*16384;
                const uint32_t tgB = sb + OFF_TGTB + (uint32_t)kc*16384;

                #pragma unroll
                for (int kk = 0; kk < 4; ++kk) {
                    const uint32_t uA = kk*2 + uAbit;
                    const uint32_t uB = kk*2 + uBbit;
                    uint32_t aA0[4], aA1[4], aB0[4], aB1[4];
                    uint32_t bA0[4], bA1[4], bB0[4], bB1[4];
                    LDSM4(aA0[0],aA0[1],aA0[2],aA0[3], stA + offA0 + (((uA ^ xA0)) << 4));
                    LDSM4(aA1[0],aA1[1],aA1[2],aA1[3], stA + offA1 + (((uA ^ xA1)) << 4));
                    LDSM4(bA0[0],bA0[1],bA0[2],bA0[3], tgA + offB0 + (((uB ^ xB0)) << 4));
                    LDSM4(bA1[0],bA1[1],bA1[2],bA1[3], tgA + offB1 + (((uB ^ xB1)) << 4));
                    LDSM4(aB0[0],aB0[1],aB0[2],aB0[3], stB + offA0 + (((uA ^ xA0)) << 4));
                    LDSM4(aB1[0],aB1[1],aB1[2],aB1[3], stB + offA1 + (((uA ^ xA1)) << 4));
                    LDSM4(bB0[0],bB0[1],bB0[2],bB0[3], tgB + offB0 + (((uB ^ xB0)) << 4));
                    LDSM4(bB1[0],bB1[1],bB1[2],bB1[3], tgB + offB1 + (((uB ^ xB1)) << 4));

                    MMA16816(accA[0][0], aA0, bA0[0], bA0[1]);
                    MMA16816(accA[0][1], aA0, bA0[2], bA0[3]);
                    MMA16816(accA[0][2], aA0, bA1[0], bA1[1]);
                    MMA16816(accA[0][3], aA0, bA1[2], bA1[3]);
                    MMA16816(accA[1][0], aA1, bA0[0], bA0[1]);
                    MMA16816(accA[1][1], aA1, bA0[2], bA0[3]);
                    MMA16816(accA[1][2], aA1, bA1[0], bA1[1]);
                    MMA16816(accA[1][3], aA1, bA1[2], bA1[3]);

                    MMA16816(accB[0][0], aB0, bB0[0], bB0[1]);
                    MMA16816(accB[0][1], aB0, bB0[2], bB0[3]);
                    MMA16816(accB[0][2], aB0, bB1[0], bB1[1]);
                    MMA16816(accB[0][3], aB0, bB1[2], bB1[3]);
                    MMA16816(accB[1][0], aB1, bB0[0], bB0[1]);
                    MMA16816(accB[1][1], aB1, bB0[2], bB0[3]);
                    MMA16816(accB[1][2], aB1, bB1[0], bB1[1]);
                    MMA16816(accB[1][3], aB1, bB1[2], bB1[3]);
                }
            }
        }

        // ---- epilogue: two-pass (pipelined lg2, then pipelined ex2) ----
        if (active) {
            const bool edge = diag && (wm == wn);
            // pass 1: accB <- q = clip(beta)*lg2(d)*c  (32 independent lg2)
            #pragma unroll
            for (int m = 0; m < 2; ++m) {
                #pragma unroll
                for (int n = 0; n < 4; ++n) {
                    const int c0 = wn*32 + n*8 + 2*(lane & 3);
                    #pragma unroll
                    for (int e = 0; e < 4; ++e) {
                        float tt   = sTsT[c0 + (e & 1)];
                        float beta = fminf(fmaxf(accB[m][n][e] + 1.0f, 0.0f), 10.0f);
                        float d    = fabsf(tsS[m][e >> 1] - tt) + 1e-10f;
                        accB[m][n][e] = beta * (flg2(d) * NEG_INV_LN5);
                    }
                }
            }
            // pass 2: colsum += accA * ex2(q)
            #pragma unroll
            for (int m = 0; m < 2; ++m) {
                #pragma unroll
                for (int n = 0; n < 4; ++n) {
                    #pragma unroll
                    for (int e = 0; e < 4; ++e) {
                        float cr = accA[m][n][e] * fex2(accB[m][n][e]);
                        if (edge) {
                            const int r_l = wm*32 + m*16 + (lane >> 2) + ((e < 2) ? 0 : 8);
                            const int c_l = wn*32 + n*8 + 2*(lane & 3) + (e & 1);
                            if (r_l < c_l) colsum[n][e & 1] += cr;
                        } else {
                            colsum[n][e & 1] += cr;
                        }
                    }
                }
            }
        }
    }

    // ---- cross-lane column reduce ----
    #pragma unroll
    for (int n = 0; n < 4; ++n)
        #pragma unroll
        for (int p = 0; p < 2; ++p) {
            float v = colsum[n][p];
            v += __shfl_xor_sync(0xffffffffu, v, 4);
            v += __shfl_xor_sync(0xffffffffu, v, 8);
            v += __shfl_xor_sync(0xffffffffu, v, 16);
            colsum[n][p] = v;
        }
    __syncthreads();
    if (lane < 4) {
        #pragma unroll
        for (int n = 0; n < 4; ++n) {
            int c = wn*32 + n*8 + 2*lane;
            sPart[wm*128 + c]     = colsum[n][0];
            sPart[wm*128 + c + 1] = colsum[n][1];
        }
    }
    __syncthreads();

    if (tid < 128) {
        float s = sPart[tid] + sPart[128 + tid] + sPart[256 + tid] + sPart[384 + tid];
        float h = g_bias[col_base + tid] + s;
        out[col_base + tid] = 1.0f / (1.0f + fex2(-h * 1.4426950408889634f));
    }
}

extern "C" void kernel_launch(void* const* d_in, const int* in_sizes, int n_in,
                              void* d_out, int out_size)
{
    const int*   skills   = (const int*)d_in[0];
    const int*   problems = (const int*)d_in[1];
    const int*   times    = (const int*)d_in[2];
    const int*   labels   = (const int*)d_in[3];
    const float* aI = (const float*)d_in[4];
    const float* aS = (const float*)d_in[5];
    const float* bI = (const float*)d_in[6];
    const float* bS = (const float*)d_in[7];
    const float* pb = (const float*)d_in[8];
    const float* sb = (const float*)d_in[9];
    float* out = (float*)d_out;

    static bool attr_done = false;
    if (!attr_done) {
        cudaFuncSetAttribute(hawkes_mma, cudaFuncAttributeMaxDynamicSharedMemorySize, SMEM_BYTES);
        attr_done = true;
    }

    int total = NPOS * (EMB/4);
    gather_kernel<<<(total + 255) / 256, 256>>>(skills, problems, times, labels,
                                                aI, aS, bI, bS, pb, sb);
    hawkes_mma<<<NT128 * BB, 512, SMEM_BYTES>>>(out);
}